// round 6
// baseline (speedup 1.0000x reference)
#include <cuda_runtime.h>
#include <cuda_bf16.h>
#include <cstdint>

// ---------------------------------------------------------------------------
// Child-Sum Tree-LSTM, complete 4-ary tree depth 7.
// N_NODES=21845, N_INTERNAL=5461, HID=IN=512.
//
// Key structure: children of internal level l (rows [s,e)) are EXACTLY the
// contiguous rows [4s+1, 4e+1) = all of level l+1. So all recurrent GEMMs are
// plain (no gather):
//   hsum[M x512]  = sum of 4 consecutive h rows of level l+1
//   iou [M x1536] = hsum @ U_iou^T
//   f   [4M x512] = h(level l+1) @ U_f^T
// Big GEMM: wx[5461 x 2048] = x @ [W_iou; W_f]^T + [b_iou; b_f], written as
// two GEMMs with ldc=2048 (no packing pass).
// All fp32, double-buffered SGEMM. Fast tanh.approx activations.
// ---------------------------------------------------------------------------

#define N_NODES    21845
#define N_INTERNAL 5461
#define HID        512
#define KDIM       512

// Static scratch (no allocation allowed in kernel_launch)
__device__ float g_wx[N_INTERNAL * 2048];      // ~44.7 MB
__device__ float g_iou[1024 * 1536];           // 6 MB  (max level M = 1024)
__device__ float g_f[4096 * 512];              // 8 MB  (max 4M = 4096 rows)
__device__ float g_hsum[1024 * 512];           // 2 MB

__device__ __forceinline__ float fast_tanh(float x) {
    float r;
    asm("tanh.approx.f32 %0, %1;" : "=f"(r) : "f"(x));
    return r;
}
__device__ __forceinline__ float fast_sigm(float x) {
    return 0.5f + 0.5f * fast_tanh(0.5f * x);
}

// ---------------------------------------------------------------------------
__global__ void zero_leaves_kernel(float4* __restrict__ h4, float4* __restrict__ c4)
{
    const int cnt = (N_NODES - N_INTERNAL) * HID / 4;   // 2,097,152
    int i = blockIdx.x * blockDim.x + threadIdx.x;
    if (i < cnt) {
        float4 z = make_float4(0.f, 0.f, 0.f, 0.f);
        h4[i] = z;
        c4[i] = z;
    }
}

// ---------------------------------------------------------------------------
// hsum[m] = sum_{j=0..3} hlev[4m+j]   (hlev = h rows of level l+1)
// ---------------------------------------------------------------------------
__global__ void hsum_kernel(const float4* __restrict__ hlev, float4* __restrict__ out, int M)
{
    int i = blockIdx.x * blockDim.x + threadIdx.x;      // over M*128 float4
    if (i >= M * 128) return;
    int m  = i >> 7;
    int sl = i & 127;
    const float4* p = hlev + (size_t)m * 512 + sl;      // 4 rows, 128 f4 apart
    float4 a = p[0], b = p[128], c = p[256], d = p[384];
    float4 r;
    r.x = a.x + b.x + c.x + d.x;
    r.y = a.y + b.y + c.y + d.y;
    r.z = a.z + b.z + c.z + d.z;
    r.w = a.w + b.w + c.w + d.w;
    out[i] = r;
}

// ---------------------------------------------------------------------------
// Double-buffered fp32 GEMM (NT): C[M,N] = A[M,K(lda)] * B[N,K]^T (+ bias)
// BMxBN tile, BK=16, TMxTN per thread, (BM/TM)*(BN/TN) threads.
// N must be a multiple of BN; K a multiple of BK; M guarded.
// ---------------------------------------------------------------------------
template<int BM, int BN, int BK, int TM, int TN>
__global__ __launch_bounds__((BM/TM)*(BN/TN), 2)
void sgemm_db(const float* __restrict__ A, int lda,
              const float* __restrict__ B,
              float* __restrict__ C, int ldc,
              const float* __restrict__ bias,
              int M, int N, int K)
{
    constexpr int NT = (BM/TM)*(BN/TN);
    constexpr int A4 = BM*BK/4;                 // float4 per A stage
    constexpr int B4 = BN*BK/4;
    constexpr int LA = (A4 + NT - 1)/NT;
    constexpr int LB = (B4 + NT - 1)/NT;
    constexpr int KV = BK/4;

    __shared__ float As[2][BK][BM];
    __shared__ float Bs[2][BK][BN];

    const int t  = threadIdx.x;
    const int bm = blockIdx.y * BM;
    const int bn = blockIdx.x * BN;
    const int tx = t % (BN/TN);
    const int ty = t / (BN/TN);

    float4 ra[LA], rb[LB];

    auto loadA = [&](int k0) {
#pragma unroll
        for (int i = 0; i < LA; i++) {
            int flat = t + i*NT;
            ra[i] = make_float4(0.f, 0.f, 0.f, 0.f);
            if (flat < A4) {
                int row = flat / KV;
                int ks  = (flat % KV) * 4;
                int gm  = bm + row;
                if (gm < M)
                    ra[i] = *reinterpret_cast<const float4*>(A + (size_t)gm*lda + k0 + ks);
            }
        }
    };
    auto loadB = [&](int k0) {
#pragma unroll
        for (int i = 0; i < LB; i++) {
            int flat = t + i*NT;
            if (flat < B4) {
                int row = flat / KV;
                int ks  = (flat % KV) * 4;
                rb[i] = *reinterpret_cast<const float4*>(B + (size_t)(bn + row)*K + k0 + ks);
            }
        }
    };
    auto storeA = [&](int buf) {
#pragma unroll
        for (int i = 0; i < LA; i++) {
            int flat = t + i*NT;
            if (flat < A4) {
                int row = flat / KV;
                int ks  = (flat % KV) * 4;
                As[buf][ks+0][row] = ra[i].x;
                As[buf][ks+1][row] = ra[i].y;
                As[buf][ks+2][row] = ra[i].z;
                As[buf][ks+3][row] = ra[i].w;
            }
        }
    };
    auto storeB = [&](int buf) {
#pragma unroll
        for (int i = 0; i < LB; i++) {
            int flat = t + i*NT;
            if (flat < B4) {
                int row = flat / KV;
                int ks  = (flat % KV) * 4;
                Bs[buf][ks+0][row] = rb[i].x;
                Bs[buf][ks+1][row] = rb[i].y;
                Bs[buf][ks+2][row] = rb[i].z;
                Bs[buf][ks+3][row] = rb[i].w;
            }
        }
    };

    float acc[TM][TN];
#pragma unroll
    for (int i = 0; i < TM; i++)
#pragma unroll
        for (int j = 0; j < TN; j++) acc[i][j] = 0.f;

    loadA(0); loadB(0);
    storeA(0); storeB(0);
    __syncthreads();

    const int nit = K / BK;
    int cur = 0;
    for (int it = 0; it < nit; it++) {
        if (it + 1 < nit) { loadA((it+1)*BK); loadB((it+1)*BK); }

#pragma unroll
        for (int kk = 0; kk < BK; kk++) {
            float a[TM], b[TN];
#pragma unroll
            for (int i = 0; i < TM; i++) a[i] = As[cur][kk][ty*TM + i];
#pragma unroll
            for (int j = 0; j < TN; j++) b[j] = Bs[cur][kk][tx*TN + j];
#pragma unroll
            for (int i = 0; i < TM; i++)
#pragma unroll
                for (int j = 0; j < TN; j++) acc[i][j] += a[i] * b[j];
        }

        if (it + 1 < nit) {
            storeA(1 - cur); storeB(1 - cur);
            __syncthreads();
            cur ^= 1;
        }
    }

    // epilogue (float4 stores; BN, tx*TN 4-aligned, ldc multiple of 4)
#pragma unroll
    for (int i = 0; i < TM; i++) {
        int r = bm + ty*TM + i;
        if (r >= M) continue;
        float* cp = C + (size_t)r * ldc + bn + tx*TN;
#pragma unroll
        for (int j0 = 0; j0 < TN; j0 += 4) {
            float4 v;
            v.x = acc[i][j0+0]; v.y = acc[i][j0+1];
            v.z = acc[i][j0+2]; v.w = acc[i][j0+3];
            if (bias) {
                const float* bp = bias + bn + tx*TN + j0;
                v.x += bp[0]; v.y += bp[1]; v.z += bp[2]; v.w += bp[3];
            }
            *reinterpret_cast<float4*>(cp + j0) = v;
        }
    }
}

// ---------------------------------------------------------------------------
// Level 6: children are leaves (h=c=0) -> pure activation from wx.
// ---------------------------------------------------------------------------
__global__ __launch_bounds__(512)
void act6_kernel(float* __restrict__ h_arr, float* __restrict__ c_arr, int s)
{
    int n = blockIdx.x;
    int d = threadIdx.x;
    const float* wxp = g_wx + (size_t)(s + n) * 2048;
    float i = fast_sigm(wxp[d]);
    float o = fast_sigm(wxp[512 + d]);
    float u = fast_tanh(wxp[1024 + d]);
    float c = i * u;
    c_arr[(size_t)(s + n) * HID + d] = c;
    h_arr[(size_t)(s + n) * HID + d] = o * fast_tanh(c);
}

// ---------------------------------------------------------------------------
// Level combine: children of node s+n are rows 4(s+n)+1 .. +4.
//   iou_pre = g_iou[n] + wx_iou ;  f_j = g_f[4n+j] + wx_f (NO sigmoid)
//   c_new = sig(i)*tanh(u) + sum_j f_j * c_child_j ; h = sig(o)*tanh(c_new)
// ---------------------------------------------------------------------------
__global__ __launch_bounds__(512)
void combine_kernel(float* __restrict__ h_arr, float* __restrict__ c_arr, int s)
{
    int n = blockIdx.x;
    int d = threadIdx.x;
    const float* wxp  = g_wx  + (size_t)(s + n) * 2048;
    const float* ioup = g_iou + (size_t)n * 1536;

    float i = fast_sigm(ioup[d]        + wxp[d]);
    float o = fast_sigm(ioup[512 + d]  + wxp[512 + d]);
    float u = fast_tanh(ioup[1024 + d] + wxp[1024 + d]);
    float wxf = wxp[1536 + d];

    float acc = i * u;
    int cbase = 4 * (s + n) + 1;
#pragma unroll
    for (int j = 0; j < 4; j++) {
        float fj = g_f[((size_t)n * 4 + j) * 512 + d] + wxf;
        acc += fj * c_arr[(size_t)(cbase + j) * HID + d];
    }
    c_arr[(size_t)(s + n) * HID + d] = acc;
    h_arr[(size_t)(s + n) * HID + d] = o * fast_tanh(acc);
}

// ---------------------------------------------------------------------------
extern "C" void kernel_launch(void* const* d_in, const int* in_sizes, int n_in,
                              void* d_out, int out_size)
{
    const float* x      = (const float*)d_in[0];
    const float* W_iou  = (const float*)d_in[2];
    const float* b_iou  = (const float*)d_in[3];
    const float* W_f    = (const float*)d_in[4];
    const float* b_f    = (const float*)d_in[5];
    const float* U_iou  = (const float*)d_in[6];
    const float* U_f    = (const float*)d_in[7];

    float* h_arr = (float*)d_out;
    float* c_arr = (float*)d_out + (size_t)N_NODES * HID;

    float *wx, *iou, *fbuf, *hsum;
    cudaGetSymbolAddress((void**)&wx,   g_wx);
    cudaGetSymbolAddress((void**)&iou,  g_iou);
    cudaGetSymbolAddress((void**)&fbuf, g_f);
    cudaGetSymbolAddress((void**)&hsum, g_hsum);

    // 1. zero leaf rows of h and c
    {
        float4* h4 = (float4*)(h_arr + (size_t)N_INTERNAL * HID);
        float4* c4 = (float4*)(c_arr + (size_t)N_INTERNAL * HID);
        int cnt = (N_NODES - N_INTERNAL) * HID / 4;
        zero_leaves_kernel<<<(cnt + 255) / 256, 256>>>(h4, c4);
    }

    // 2. wx = x @ [W_iou; W_f]^T + bias, as two GEMMs into strided wx
    {
        dim3 g1(1536 / 128, (N_INTERNAL + 127) / 128);
        sgemm_db<128,128,16,8,8><<<g1, 256>>>(x, KDIM, W_iou, wx, 2048, b_iou,
                                              N_INTERNAL, 1536, KDIM);
        dim3 g2(512 / 128, (N_INTERNAL + 127) / 128);
        sgemm_db<128,128,16,8,8><<<g2, 256>>>(x, KDIM, W_f, wx + 1536, 2048, b_f,
                                              N_INTERNAL, 512, KDIM);
    }

    // 3. level 6: nodes [1365, 5461), pure activation
    act6_kernel<<<4096, 512>>>(h_arr, c_arr, 1365);

    // 4. levels 5..0
    for (int l = 5; l >= 0; --l) {
        int M  = 1 << (2 * l);
        int s  = (M - 1) / 3;          // level start
        int sp = 4 * s + 1;            // level l+1 start (children rows)
        const float* hlev = h_arr + (size_t)sp * HID;

        // hsum[M x 512]
        hsum_kernel<<<(M * 128 + 255) / 256, 256>>>(
            (const float4*)hlev, (float4*)hsum, M);

        // iou[M x 1536] = hsum @ U_iou^T
        if (M >= 128) {
            dim3 g(1536 / 128, (M + 127) / 128);
            sgemm_db<128,128,16,8,8><<<g, 256>>>(hsum, KDIM, U_iou, iou, 1536,
                                                 nullptr, M, 1536, KDIM);
        } else {
            dim3 g(1536 / 128, (M + 31) / 32);
            sgemm_db<32,128,16,2,8><<<g, 256>>>(hsum, KDIM, U_iou, iou, 1536,
                                                nullptr, M, 1536, KDIM);
        }

        // f[4M x 512] = h(level l+1) @ U_f^T
        int Mf = 4 * M;
        if (Mf >= 128) {
            dim3 g(512 / 128, (Mf + 127) / 128);
            sgemm_db<128,128,16,8,8><<<g, 256>>>(hlev, KDIM, U_f, fbuf, 512,
                                                 nullptr, Mf, 512, KDIM);
        } else {
            dim3 g(512 / 128, (Mf + 31) / 32);
            sgemm_db<32,128,16,2,8><<<g, 256>>>(hlev, KDIM, U_f, fbuf, 512,
                                                nullptr, Mf, 512, KDIM);
        }

        // gates + cell/hidden update
        combine_kernel<<<M, 512>>>(h_arr, c_arr, s);
    }
}

// round 11
// speedup vs baseline: 1.6559x; 1.6559x over previous
#include <cuda_runtime.h>
#include <cuda_bf16.h>
#include <cstdint>

// ---------------------------------------------------------------------------
// Child-Sum Tree-LSTM, complete 4-ary tree depth 7.
// N_NODES=21845, N_INTERNAL=5461, HID=IN=512.
// Children of level-l rows [s,e) are exactly contiguous rows [4s+1,4e+1).
// Pipeline:
//   wx[5461x2048] = x @ [W_iou;W_f]^T + bias      (two GEMMs, ldc=2048)
//   level 6: pure activation (children are leaves, h=c=0)
//   levels 5..0: hsum -> iou GEMM -> f GEMM -> combine
// GEMM inner product uses packed fma.rn.f32x2 (FFMA2): 2x fp32 FLOP/issue,
// bit-identical rounding to scalar FFMA.
// (Round 7 = resubmit of round 6: infra failure, theory still unmeasured.)
// ---------------------------------------------------------------------------

#define N_NODES    21845
#define N_INTERNAL 5461
#define HID        512
#define KDIM       512

__device__ float g_wx[N_INTERNAL * 2048];      // ~44.7 MB
__device__ float g_iou[1024 * 1536];           // 6 MB
__device__ float g_f[4096 * 512];              // 8 MB
__device__ float g_hsum[1024 * 512];           // 2 MB

__device__ __forceinline__ float fast_tanh(float x) {
    float r;
    asm("tanh.approx.f32 %0, %1;" : "=f"(r) : "f"(x));
    return r;
}
__device__ __forceinline__ float fast_sigm(float x) {
    return 0.5f + 0.5f * fast_tanh(0.5f * x);
}

// ---------------------------------------------------------------------------
__global__ void zero_leaves_kernel(float4* __restrict__ h4, float4* __restrict__ c4)
{
    const int cnt = (N_NODES - N_INTERNAL) * HID / 4;
    int i = blockIdx.x * blockDim.x + threadIdx.x;
    if (i < cnt) {
        float4 z = make_float4(0.f, 0.f, 0.f, 0.f);
        h4[i] = z;
        c4[i] = z;
    }
}

// hsum[m] = sum_{j=0..3} hlev[4m+j]
__global__ void hsum_kernel(const float4* __restrict__ hlev, float4* __restrict__ out, int M)
{
    int i = blockIdx.x * blockDim.x + threadIdx.x;
    if (i >= M * 128) return;
    int m  = i >> 7;
    int sl = i & 127;
    const float4* p = hlev + (size_t)m * 512 + sl;
    float4 a = p[0], b = p[128], c = p[256], d = p[384];
    float4 r;
    r.x = a.x + b.x + c.x + d.x;
    r.y = a.y + b.y + c.y + d.y;
    r.z = a.z + b.z + c.z + d.z;
    r.w = a.w + b.w + c.w + d.w;
    out[i] = r;
}

// ---------------------------------------------------------------------------
// FFMA2 SGEMM (NT): C[M,N] = A[M,K(lda)] * B[N,K]^T (+ col bias)
// Double-buffered smem + register prefetch. NO minBlocks launch bound
// (round-5 regression: forced reg cap -> spills).
// Requirements: N % BN == 0, K % BK == 0, NT == (BM/TM)*(BN/TN) == 256,
//               (BM*BK/4) % NT == 0 or == NT, TN % 4 == 0, ldc % 4 == 0.
// ---------------------------------------------------------------------------
template<int BM, int BN, int BK, int TM, int TN>
__global__ __launch_bounds__((BM/TM)*(BN/TN))
void sgemm2(const float* __restrict__ A, int lda,
            const float* __restrict__ B,
            float* __restrict__ C, int ldc,
            const float* __restrict__ bias,
            int M, int N, int K)
{
    constexpr int NT = (BM/TM)*(BN/TN);
    constexpr int KV = BK/4;
    constexpr int A4 = BM*BK/4;
    constexpr int B4 = BN*BK/4;
    constexpr int LA = (A4 + NT - 1)/NT;
    constexpr int LB = (B4 + NT - 1)/NT;
    static_assert(B4 % NT == 0, "B tile must divide evenly");
    static_assert(TN % 4 == 0, "TN multiple of 4");

    __shared__ __align__(16) float As[2][BK][BM];
    __shared__ __align__(16) float Bs[2][BK][BN];

    const int t  = threadIdx.x;
    const int bm = blockIdx.y * BM;
    const int bn = blockIdx.x * BN;
    const int tx = t % (BN/TN);
    const int ty = t / (BN/TN);

    float4 ra[LA], rb[LB];

    // accumulators: TM x (TN/2) packed f32x2
    unsigned long long acc2[TM][TN/2];
#pragma unroll
    for (int i = 0; i < TM; i++)
#pragma unroll
        for (int j = 0; j < TN/2; j++) acc2[i][j] = 0ULL;

#define LOAD_TILES(k0)                                                         \
    {                                                                          \
        _Pragma("unroll")                                                      \
        for (int i = 0; i < LA; i++) {                                         \
            int flat = t + i*NT;                                               \
            ra[i] = make_float4(0.f,0.f,0.f,0.f);                              \
            if (A4 % NT == 0 || flat < A4) {                                   \
                int row = flat / KV, ks = (flat % KV)*4;                       \
                int gm = bm + row;                                             \
                if (gm < M)                                                    \
                    ra[i] = *reinterpret_cast<const float4*>(                  \
                        A + (size_t)gm*lda + (k0) + ks);                       \
            }                                                                  \
        }                                                                      \
        _Pragma("unroll")                                                      \
        for (int i = 0; i < LB; i++) {                                         \
            int flat = t + i*NT;                                               \
            int row = flat / KV, ks = (flat % KV)*4;                           \
            rb[i] = *reinterpret_cast<const float4*>(                          \
                B + (size_t)(bn + row)*K + (k0) + ks);                         \
        }                                                                      \
    }

#define STORE_TILES(buf)                                                       \
    {                                                                          \
        _Pragma("unroll")                                                      \
        for (int i = 0; i < LA; i++) {                                         \
            int flat = t + i*NT;                                               \
            if (A4 % NT == 0 || flat < A4) {                                   \
                int row = flat / KV, ks = (flat % KV)*4;                       \
                As[buf][ks+0][row] = ra[i].x;                                  \
                As[buf][ks+1][row] = ra[i].y;                                  \
                As[buf][ks+2][row] = ra[i].z;                                  \
                As[buf][ks+3][row] = ra[i].w;                                  \
            }                                                                  \
        }                                                                      \
        _Pragma("unroll")                                                      \
        for (int i = 0; i < LB; i++) {                                         \
            int flat = t + i*NT;                                               \
            int row = flat / KV, ks = (flat % KV)*4;                           \
            Bs[buf][ks+0][row] = rb[i].x;                                      \
            Bs[buf][ks+1][row] = rb[i].y;                                      \
            Bs[buf][ks+2][row] = rb[i].z;                                      \
            Bs[buf][ks+3][row] = rb[i].w;                                      \
        }                                                                      \
    }

    LOAD_TILES(0);
    STORE_TILES(0);
    __syncthreads();

    const int nit = K / BK;
    int cur = 0;
#pragma unroll 1
    for (int it = 0; it < nit; it++) {
        if (it + 1 < nit) LOAD_TILES((it+1)*BK);

#pragma unroll
        for (int kk = 0; kk < BK; kk++) {
            // B operand: packed pairs straight out of shared memory
            unsigned long long b2[TN/2];
#pragma unroll
            for (int j = 0; j < TN/4; j++) {
                ulonglong2 v = *reinterpret_cast<const ulonglong2*>(
                    &Bs[cur][kk][tx*TN + 4*j]);
                b2[2*j]   = v.x;
                b2[2*j+1] = v.y;
            }
#pragma unroll
            for (int i = 0; i < TM; i++) {
                unsigned int au = __float_as_uint(As[cur][kk][ty*TM + i]);
                unsigned long long a2;
                asm("mov.b64 %0, {%1, %1};" : "=l"(a2) : "r"(au));
#pragma unroll
                for (int j = 0; j < TN/2; j++)
                    asm("fma.rn.f32x2 %0, %1, %2, %0;"
                        : "+l"(acc2[i][j]) : "l"(a2), "l"(b2[j]));
            }
        }

        if (it + 1 < nit) {
            STORE_TILES(1 - cur);
            __syncthreads();
            cur ^= 1;
        }
    }
#undef LOAD_TILES
#undef STORE_TILES

    // epilogue
#pragma unroll
    for (int i = 0; i < TM; i++) {
        int r = bm + ty*TM + i;
        if (r >= M) continue;
        float* cp = C + (size_t)r * ldc + bn + tx*TN;
#pragma unroll
        for (int j0 = 0; j0 < TN; j0 += 4) {
            unsigned int l0, h0, l1, h1;
            asm("mov.b64 {%0, %1}, %2;" : "=r"(l0), "=r"(h0) : "l"(acc2[i][j0/2]));
            asm("mov.b64 {%0, %1}, %2;" : "=r"(l1), "=r"(h1) : "l"(acc2[i][j0/2+1]));
            float4 v;
            v.x = __uint_as_float(l0); v.y = __uint_as_float(h0);
            v.z = __uint_as_float(l1); v.w = __uint_as_float(h1);
            if (bias) {
                const float* bp = bias + bn + tx*TN + j0;
                v.x += bp[0]; v.y += bp[1]; v.z += bp[2]; v.w += bp[3];
            }
            *reinterpret_cast<float4*>(cp + j0) = v;
        }
    }
}

// ---------------------------------------------------------------------------
// Level 6: children are leaves -> pure activation from wx.
__global__ __launch_bounds__(512)
void act6_kernel(float* __restrict__ h_arr, float* __restrict__ c_arr, int s)
{
    int n = blockIdx.x;
    int d = threadIdx.x;
    const float* wxp = g_wx + (size_t)(s + n) * 2048;
    float i = fast_sigm(wxp[d]);
    float o = fast_sigm(wxp[512 + d]);
    float u = fast_tanh(wxp[1024 + d]);
    float c = i * u;
    c_arr[(size_t)(s + n) * HID + d] = c;
    h_arr[(size_t)(s + n) * HID + d] = o * fast_tanh(c);
}

// Level combine: children of node s+n are rows 4(s+n)+1 .. +4.
__global__ __launch_bounds__(512)
void combine_kernel(float* __restrict__ h_arr, float* __restrict__ c_arr, int s)
{
    int n = blockIdx.x;
    int d = threadIdx.x;
    const float* wxp  = g_wx  + (size_t)(s + n) * 2048;
    const float* ioup = g_iou + (size_t)n * 1536;

    float i = fast_sigm(ioup[d]        + wxp[d]);
    float o = fast_sigm(ioup[512 + d]  + wxp[512 + d]);
    float u = fast_tanh(ioup[1024 + d] + wxp[1024 + d]);
    float wxf = wxp[1536 + d];

    float acc = i * u;
    int cbase = 4 * (s + n) + 1;
#pragma unroll
    for (int j = 0; j < 4; j++) {
        float fj = g_f[((size_t)n * 4 + j) * 512 + d] + wxf;
        acc += fj * c_arr[(size_t)(cbase + j) * HID + d];
    }
    c_arr[(size_t)(s + n) * HID + d] = acc;
    h_arr[(size_t)(s + n) * HID + d] = o * fast_tanh(acc);
}

// ---------------------------------------------------------------------------
extern "C" void kernel_launch(void* const* d_in, const int* in_sizes, int n_in,
                              void* d_out, int out_size)
{
    const float* x      = (const float*)d_in[0];
    const float* W_iou  = (const float*)d_in[2];
    const float* b_iou  = (const float*)d_in[3];
    const float* W_f    = (const float*)d_in[4];
    const float* b_f    = (const float*)d_in[5];
    const float* U_iou  = (const float*)d_in[6];
    const float* U_f    = (const float*)d_in[7];

    float* h_arr = (float*)d_out;
    float* c_arr = (float*)d_out + (size_t)N_NODES * HID;

    float *wx, *iou, *fbuf, *hsum;
    cudaGetSymbolAddress((void**)&wx,   g_wx);
    cudaGetSymbolAddress((void**)&iou,  g_iou);
    cudaGetSymbolAddress((void**)&fbuf, g_f);
    cudaGetSymbolAddress((void**)&hsum, g_hsum);

    // 1. zero leaf rows of h and c
    {
        float4* h4 = (float4*)(h_arr + (size_t)N_INTERNAL * HID);
        float4* c4 = (float4*)(c_arr + (size_t)N_INTERNAL * HID);
        int cnt = (N_NODES - N_INTERNAL) * HID / 4;
        zero_leaves_kernel<<<(cnt + 255) / 256, 256>>>(h4, c4);
    }

    // 2. wx = x @ [W_iou; W_f]^T + bias  (two GEMMs into strided wx)
    {
        dim3 g1(1536 / 128, (N_INTERNAL + 127) / 128);
        sgemm2<128,128,8,8,8><<<g1, 256>>>(x, KDIM, W_iou, wx, 2048, b_iou,
                                           N_INTERNAL, 1536, KDIM);
        dim3 g2(512 / 128, (N_INTERNAL + 127) / 128);
        sgemm2<128,128,8,8,8><<<g2, 256>>>(x, KDIM, W_f, wx + 1536, 2048, b_f,
                                           N_INTERNAL, 512, KDIM);
    }

    // 3. level 6: nodes [1365, 5461), pure activation
    act6_kernel<<<4096, 512>>>(h_arr, c_arr, 1365);

    // 4. levels 5..0
    for (int l = 5; l >= 0; --l) {
        int M  = 1 << (2 * l);
        int s  = (M - 1) / 3;
        int sp = 4 * s + 1;                       // level l+1 start
        const float* hlev = h_arr + (size_t)sp * HID;

        hsum_kernel<<<(M * 128 + 255) / 256, 256>>>(
            (const float4*)hlev, (float4*)hsum, M);

        // iou[M x 1536] = hsum @ U_iou^T
        if (M >= 1024) {
            dim3 g(1536 / 128, M / 64);
            sgemm2<64,128,16,4,8><<<g, 256>>>(hsum, KDIM, U_iou, iou, 1536,
                                              nullptr, M, 1536, KDIM);
        } else {
            dim3 g(1536 / 128, (M + 31) / 32);
            sgemm2<32,128,32,2,8><<<g, 256>>>(hsum, KDIM, U_iou, iou, 1536,
                                              nullptr, M, 1536, KDIM);
        }

        // f[4M x 512] = h(level l+1) @ U_f^T
        int Mf = 4 * M;
        if (Mf >= 4096) {
            dim3 g(512 / 128, Mf / 64);
            sgemm2<64,128,16,4,8><<<g, 256>>>(hlev, KDIM, U_f, fbuf, 512,
                                              nullptr, Mf, 512, KDIM);
        } else {
            dim3 g(512 / 128, (Mf + 31) / 32);
            sgemm2<32,128,32,2,8><<<g, 256>>>(hlev, KDIM, U_f, fbuf, 512,
                                              nullptr, Mf, 512, KDIM);
        }

        combine_kernel<<<M, 512>>>(h_arr, c_arr, s);
    }
}

// round 12
// speedup vs baseline: 2.7740x; 1.6752x over previous
#include <cuda_runtime.h>
#include <cuda_bf16.h>
#include <cstdint>

// ---------------------------------------------------------------------------
// Child-Sum Tree-LSTM, complete 4-ary tree depth 7.
// N_NODES=21845, N_INTERNAL=5461, HID=IN=512.
// Children of level-l rows [s,e) are exactly rows [4s+1, 4e+1) (level l+1).
//
// GEMMs run on tensor cores via mma.sync.m16n8k16 bf16 with SPLIT-BF16
// 3-term fp32 emulation packed along K:
//   A' = [Ahi | Ahi | Alo]  (K'=1536)      "A pattern"
//   B' = [Bhi | Blo | Bhi]                  "B pattern"
//   C  = A'.B'^T = Ahi.Bhi + Ahi.Blo + Alo.Bhi   (error ~2^-17, fp32 accum)
// Pipeline:
//   conv x/W/U -> one big GEMM wx[5461x2048] -> act6 -> per level:
//   hsum+conv -> iou GEMM -> f GEMM -> combine (also emits bf16 split h)
// ---------------------------------------------------------------------------

#define N_NODES    21845
#define N_INTERNAL 5461
#define HID        512
#define KP         1536          // packed K' = 3*512

// fp32 scratch
__device__ float g_wx[N_INTERNAL * 2048];      // ~44.7 MB
__device__ float g_iou[1024 * 1536];           // 6 MB
__device__ float g_f[4096 * 512];              // 8 MB
__device__ float g_bias[2048];

// bf16 split operands
__device__ __nv_bfloat16 g_xb [N_INTERNAL * KP];   // x,   A pattern
__device__ __nv_bfloat16 g_Wb [2048 * KP];         // [W_iou;W_f], B pattern
__device__ __nv_bfloat16 g_Uib[1536 * KP];         // U_iou, B pattern
__device__ __nv_bfloat16 g_Ufb[ 512 * KP];         // U_f,   B pattern
__device__ __nv_bfloat16 g_hsb[1024 * KP];         // hsum,  A pattern
__device__ __nv_bfloat16 g_hlb[4096 * KP];         // h level rows, A pattern

__device__ __forceinline__ float fast_tanh(float x) {
    float r;
    asm("tanh.approx.f32 %0, %1;" : "=f"(r) : "f"(x));
    return r;
}
__device__ __forceinline__ float fast_sigm(float x) {
    return 0.5f + 0.5f * fast_tanh(0.5f * x);
}
__device__ __forceinline__ void split_bf16(float v, __nv_bfloat16& hi, __nv_bfloat16& lo) {
    hi = __float2bfloat16_rn(v);
    lo = __float2bfloat16_rn(v - __bfloat162float(hi));
}

// ---------------------------------------------------------------------------
__global__ void zero_leaves_kernel(float4* __restrict__ h4, float4* __restrict__ c4)
{
    const int cnt = (N_NODES - N_INTERNAL) * HID / 4;
    int i = blockIdx.x * blockDim.x + threadIdx.x;
    if (i < cnt) {
        float4 z = make_float4(0.f, 0.f, 0.f, 0.f);
        h4[i] = z;
        c4[i] = z;
    }
}

// x -> A-pattern split
__global__ void conv_x_kernel(const float* __restrict__ x)
{
    int i = blockIdx.x * blockDim.x + threadIdx.x;    // over N_INTERNAL*512
    if (i >= N_INTERNAL * 512) return;
    int m = i >> 9, k = i & 511;
    __nv_bfloat16 hi, lo;
    split_bf16(x[(size_t)m * 512 + k], hi, lo);
    __nv_bfloat16* d = g_xb + (size_t)m * KP;
    d[k] = hi; d[512 + k] = hi; d[1024 + k] = lo;
}

// [W_iou; W_f] -> B-pattern split (+ bias pack)
__global__ void conv_w_kernel(const float* __restrict__ W_iou, const float* __restrict__ W_f,
                              const float* __restrict__ b_iou, const float* __restrict__ b_f)
{
    int i = blockIdx.x * blockDim.x + threadIdx.x;    // over 2048*512
    if (i < 2048) g_bias[i] = (i < 1536) ? b_iou[i] : b_f[i - 1536];
    if (i >= 2048 * 512) return;
    int n = i >> 9, k = i & 511;
    float v = (n < 1536) ? W_iou[(size_t)n * 512 + k] : W_f[(size_t)(n - 1536) * 512 + k];
    __nv_bfloat16 hi, lo;
    split_bf16(v, hi, lo);
    __nv_bfloat16* d = g_Wb + (size_t)n * KP;
    d[k] = hi; d[512 + k] = lo; d[1024 + k] = hi;
}

// generic U -> B-pattern split
__global__ void conv_u_kernel(const float* __restrict__ U, __nv_bfloat16* __restrict__ dst, int rows)
{
    int i = blockIdx.x * blockDim.x + threadIdx.x;    // over rows*512
    if (i >= rows * 512) return;
    int n = i >> 9, k = i & 511;
    __nv_bfloat16 hi, lo;
    split_bf16(U[(size_t)n * 512 + k], hi, lo);
    __nv_bfloat16* d = dst + (size_t)n * KP;
    d[k] = hi; d[512 + k] = lo; d[1024 + k] = hi;
}

// hsum over 4 consecutive h rows -> A-pattern split
__global__ void hsum_conv_kernel(const float* __restrict__ hlev, int M)
{
    int i = blockIdx.x * blockDim.x + threadIdx.x;    // over M*512
    if (i >= M * 512) return;
    int m = i >> 9, k = i & 511;
    const float* p = hlev + (size_t)m * 2048 + k;     // 4 rows of 512
    float s = p[0] + p[512] + p[1024] + p[1536];
    __nv_bfloat16 hi, lo;
    split_bf16(s, hi, lo);
    __nv_bfloat16* d = g_hsb + (size_t)m * KP;
    d[k] = hi; d[512 + k] = hi; d[1024 + k] = lo;
}

// ---------------------------------------------------------------------------
// bf16 tensor-core GEMM (NT): C[M,N] = A'[M,KP] * B'[N,KP]^T (+ col bias)
// BM=BN=128, BK=32 (16 k-pairs/stage), 256 threads = 8 warps (4x2),
// warp tile 32x64 = 2x8 m16n8k16 mma tiles. Double-buffered smem, packed
// b16x2 k-pair layout [kp][row] with +8 u32 row padding (conflict-free).
// Requires N % 128 == 0 (true: 2048/1536/512); M guarded.
// ---------------------------------------------------------------------------
#define GSTR 136   // 128 + 8 padding, u32 units

__global__ __launch_bounds__(256)
void gemm_bf16_3x(const __nv_bfloat16* __restrict__ A,
                  const __nv_bfloat16* __restrict__ B,
                  float* __restrict__ C, int ldc,
                  const float* __restrict__ bias,
                  int M, int N)
{
    __shared__ uint32_t Ap[2][16][GSTR];
    __shared__ uint32_t Bp[2][16][GSTR];

    const int t    = threadIdx.x;
    const int lane = t & 31;
    const int warp = t >> 5;
    const int g    = lane >> 2;        // 0..7
    const int tg   = lane & 3;         // 0..3
    const int wm   = warp & 3;         // 0..3  (M dir)
    const int wn   = warp >> 2;        // 0..1  (N dir)
    const int bm   = blockIdx.y * 128;
    const int bn   = blockIdx.x * 128;

    // loader mapping: 2 float4 per thread per operand per stage
    const int lrow0 = t >> 2;          // 0..63
    const int lseg  = t & 3;           // float4 index within 32-elem row chunk

    float acc[2][8][4];
#pragma unroll
    for (int mt = 0; mt < 2; mt++)
#pragma unroll
        for (int nt = 0; nt < 8; nt++)
#pragma unroll
            for (int r = 0; r < 4; r++) acc[mt][nt][r] = 0.f;

    uint4 ar[2], br[2];

    auto load_stage = [&](int k0) {
#pragma unroll
        for (int i = 0; i < 2; i++) {
            int row = lrow0 + i * 64;
            int gm  = bm + row;
            ar[i] = make_uint4(0u, 0u, 0u, 0u);
            if (gm < M)
                ar[i] = *reinterpret_cast<const uint4*>(A + (size_t)gm * KP + k0 + lseg * 8);
            br[i] = *reinterpret_cast<const uint4*>(B + (size_t)(bn + row) * KP + k0 + lseg * 8);
        }
    };
    auto store_stage = [&](int buf) {
#pragma unroll
        for (int i = 0; i < 2; i++) {
            int row = lrow0 + i * 64;
            int kp  = lseg * 4;
            Ap[buf][kp+0][row] = ar[i].x;
            Ap[buf][kp+1][row] = ar[i].y;
            Ap[buf][kp+2][row] = ar[i].z;
            Ap[buf][kp+3][row] = ar[i].w;
            Bp[buf][kp+0][row] = br[i].x;
            Bp[buf][kp+1][row] = br[i].y;
            Bp[buf][kp+2][row] = br[i].z;
            Bp[buf][kp+3][row] = br[i].w;
        }
    };

    load_stage(0);
    store_stage(0);
    __syncthreads();

    const int nit = KP / 32;           // 48
    int cur = 0;
#pragma unroll 1
    for (int it = 0; it < nit; it++) {
        if (it + 1 < nit) load_stage((it + 1) * 32);

#pragma unroll
        for (int ks = 0; ks < 2; ks++) {
            // B fragments for all 8 n-tiles
            uint32_t bu[8][2];
#pragma unroll
            for (int nt = 0; nt < 8; nt++) {
                int nb = wn * 64 + nt * 8 + g;
                bu[nt][0] = Bp[cur][ks * 8 + tg    ][nb];
                bu[nt][1] = Bp[cur][ks * 8 + tg + 4][nb];
            }
#pragma unroll
            for (int mt = 0; mt < 2; mt++) {
                int mb = wm * 32 + mt * 16 + g;
                uint32_t a0 = Ap[cur][ks * 8 + tg    ][mb];
                uint32_t a1 = Ap[cur][ks * 8 + tg    ][mb + 8];
                uint32_t a2 = Ap[cur][ks * 8 + tg + 4][mb];
                uint32_t a3 = Ap[cur][ks * 8 + tg + 4][mb + 8];
#pragma unroll
                for (int nt = 0; nt < 8; nt++) {
                    asm volatile(
                        "mma.sync.aligned.m16n8k16.row.col.f32.bf16.bf16.f32 "
                        "{%0,%1,%2,%3}, {%4,%5,%6,%7}, {%8,%9}, {%0,%1,%2,%3};"
                        : "+f"(acc[mt][nt][0]), "+f"(acc[mt][nt][1]),
                          "+f"(acc[mt][nt][2]), "+f"(acc[mt][nt][3])
                        : "r"(a0), "r"(a1), "r"(a2), "r"(a3),
                          "r"(bu[nt][0]), "r"(bu[nt][1]));
                }
            }
        }

        if (it + 1 < nit) {
            store_stage(1 - cur);
            __syncthreads();
            cur ^= 1;
        }
    }

    // epilogue: d0:(g, 2tg) d1:(g, 2tg+1) d2:(g+8, 2tg) d3:(g+8, 2tg+1)
#pragma unroll
    for (int mt = 0; mt < 2; mt++) {
#pragma unroll
        for (int nt = 0; nt < 8; nt++) {
            int col = bn + wn * 64 + nt * 8 + tg * 2;
            float bx = 0.f, by = 0.f;
            if (bias) { bx = bias[col]; by = bias[col + 1]; }
            int r0 = bm + wm * 32 + mt * 16 + g;
            if (r0 < M) {
                float2 v = make_float2(acc[mt][nt][0] + bx, acc[mt][nt][1] + by);
                *reinterpret_cast<float2*>(C + (size_t)r0 * ldc + col) = v;
            }
            int r1 = r0 + 8;
            if (r1 < M) {
                float2 v = make_float2(acc[mt][nt][2] + bx, acc[mt][nt][3] + by);
                *reinterpret_cast<float2*>(C + (size_t)r1 * ldc + col) = v;
            }
        }
    }
}

// ---------------------------------------------------------------------------
// Level 6: children are leaves -> pure activation; also emit split-bf16 h
// into g_hlb rows 0..4095 for the level-5 f GEMM.
__global__ __launch_bounds__(512)
void act6_kernel(float* __restrict__ h_arr, float* __restrict__ c_arr, int s)
{
    int n = blockIdx.x;
    int d = threadIdx.x;
    const float* wxp = g_wx + (size_t)(s + n) * 2048;
    float i = fast_sigm(wxp[d]);
    float o = fast_sigm(wxp[512 + d]);
    float u = fast_tanh(wxp[1024 + d]);
    float c = i * u;
    float h = o * fast_tanh(c);
    c_arr[(size_t)(s + n) * HID + d] = c;
    h_arr[(size_t)(s + n) * HID + d] = h;
    __nv_bfloat16 hi, lo;
    split_bf16(h, hi, lo);
    __nv_bfloat16* hb = g_hlb + (size_t)n * KP;
    hb[d] = hi; hb[512 + d] = hi; hb[1024 + d] = lo;
}

// Level combine; also emits split-bf16 h into g_hlb row n (for next level).
__global__ __launch_bounds__(512)
void combine_kernel(float* __restrict__ h_arr, float* __restrict__ c_arr, int s)
{
    int n = blockIdx.x;
    int d = threadIdx.x;
    const float* wxp  = g_wx  + (size_t)(s + n) * 2048;
    const float* ioup = g_iou + (size_t)n * 1536;

    float i = fast_sigm(ioup[d]        + wxp[d]);
    float o = fast_sigm(ioup[512 + d]  + wxp[512 + d]);
    float u = fast_tanh(ioup[1024 + d] + wxp[1024 + d]);
    float wxf = wxp[1536 + d];

    float acc = i * u;
    int cbase = 4 * (s + n) + 1;
#pragma unroll
    for (int j = 0; j < 4; j++) {
        float fj = g_f[((size_t)n * 4 + j) * 512 + d] + wxf;
        acc += fj * c_arr[(size_t)(cbase + j) * HID + d];
    }
    float h = o * fast_tanh(acc);
    c_arr[(size_t)(s + n) * HID + d] = acc;
    h_arr[(size_t)(s + n) * HID + d] = h;
    __nv_bfloat16 hi, lo;
    split_bf16(h, hi, lo);
    __nv_bfloat16* hb = g_hlb + (size_t)n * KP;
    hb[d] = hi; hb[512 + d] = hi; hb[1024 + d] = lo;
}

// ---------------------------------------------------------------------------
extern "C" void kernel_launch(void* const* d_in, const int* in_sizes, int n_in,
                              void* d_out, int out_size)
{
    const float* x      = (const float*)d_in[0];
    const float* W_iou  = (const float*)d_in[2];
    const float* b_iou  = (const float*)d_in[3];
    const float* W_f    = (const float*)d_in[4];
    const float* b_f    = (const float*)d_in[5];
    const float* U_iou  = (const float*)d_in[6];
    const float* U_f    = (const float*)d_in[7];

    float* h_arr = (float*)d_out;
    float* c_arr = (float*)d_out + (size_t)N_NODES * HID;

    float *wx, *iou, *fbuf;
    __nv_bfloat16 *xb, *Wb, *Uib, *Ufb, *hsb, *hlb;
    cudaGetSymbolAddress((void**)&wx,  g_wx);
    cudaGetSymbolAddress((void**)&iou, g_iou);
    cudaGetSymbolAddress((void**)&fbuf,g_f);
    cudaGetSymbolAddress((void**)&xb,  g_xb);
    cudaGetSymbolAddress((void**)&Wb,  g_Wb);
    cudaGetSymbolAddress((void**)&Uib, g_Uib);
    cudaGetSymbolAddress((void**)&Ufb, g_Ufb);
    cudaGetSymbolAddress((void**)&hsb, g_hsb);
    cudaGetSymbolAddress((void**)&hlb, g_hlb);
    float* bias;
    cudaGetSymbolAddress((void**)&bias, g_bias);

    // 1. zero leaf rows of h and c
    {
        float4* h4 = (float4*)(h_arr + (size_t)N_INTERNAL * HID);
        float4* c4 = (float4*)(c_arr + (size_t)N_INTERNAL * HID);
        int cnt = (N_NODES - N_INTERNAL) * HID / 4;
        zero_leaves_kernel<<<(cnt + 255) / 256, 256>>>(h4, c4);
    }

    // 2. split-bf16 conversions
    conv_x_kernel<<<(N_INTERNAL * 512 + 255) / 256, 256>>>(x);
    conv_w_kernel<<<(2048 * 512 + 255) / 256, 256>>>(W_iou, W_f, b_iou, b_f);
    conv_u_kernel<<<(1536 * 512 + 255) / 256, 256>>>(U_iou, Uib, 1536);
    conv_u_kernel<<<( 512 * 512 + 255) / 256, 256>>>(U_f,   Ufb,  512);

    // 3. big GEMM: wx[5461 x 2048] = x' @ Wb^T + bias
    {
        dim3 g(2048 / 128, (N_INTERNAL + 127) / 128);
        gemm_bf16_3x<<<g, 256>>>(xb, Wb, wx, 2048, bias, N_INTERNAL, 2048);
    }

    // 4. level 6: nodes [1365, 5461), pure activation (+ split h emit)
    act6_kernel<<<4096, 512>>>(h_arr, c_arr, 1365);

    // 5. levels 5..0
    for (int l = 5; l >= 0; --l) {
        int M  = 1 << (2 * l);
        int s  = (M - 1) / 3;
        int sp = 4 * s + 1;                         // level l+1 start
        const float* hlev = h_arr + (size_t)sp * HID;

        // hsum + split conversion
        hsum_conv_kernel<<<(M * 512 + 255) / 256, 256>>>(hlev, M);

        // iou[M x 1536] = hsum' @ Uib^T
        {
            dim3 g(1536 / 128, (M + 127) / 128);
            gemm_bf16_3x<<<g, 256>>>(hsb, Uib, iou, 1536, nullptr, M, 1536);
        }
        // f[4M x 512] = hlev' @ Ufb^T   (reads g_hlb written by prev level)
        {
            int Mf = 4 * M;
            dim3 g(512 / 128, (Mf + 127) / 128);
            gemm_bf16_3x<<<g, 256>>>(hlb, Ufb, fbuf, 512, nullptr, Mf, 512);
        }
        // gates + cell/hidden update (+ split h emit for next level)
        combine_kernel<<<M, 512>>>(h_arr, c_arr, s);
    }
}

// round 14
// speedup vs baseline: 3.1180x; 1.1240x over previous
#include <cuda_runtime.h>
#include <cuda_bf16.h>
#include <cstdint>

// ---------------------------------------------------------------------------
// Child-Sum Tree-LSTM, complete 4-ary tree depth 7.
// N_NODES=21845, N_INTERNAL=5461, HID=IN=512.
// Children of level-l rows [s,e) are exactly rows [4s+1, 4e+1) (level l+1).
//
// GEMMs: tensor cores (mma.sync.m16n8k16.bf16) with SPLIT-BF16 3-term fp32
// emulation packed along K:  A'=[Ahi|Ahi|Alo], B'=[Bhi|Blo|Bhi], K'=1536,
// C = Ahi.Bhi + Ahi.Blo + Alo.Bhi  (error ~2^-17, fp32 accumulate).
// R14 fix: B ldmatrix must NOT use .trans (NT layout already gives the
// correct k-consecutive B fragment; .trans scrambled it -> R13 rel_err 1.34).
// ---------------------------------------------------------------------------

#define N_NODES    21845
#define N_INTERNAL 5461
#define HID        512
#define KP         1536          // packed K' = 3*512

// fp32 scratch
__device__ float g_wx[N_INTERNAL * 2048];      // ~44.7 MB
__device__ float g_iou[1024 * 1536];           // 6 MB
__device__ float g_f[4096 * 512];              // 8 MB
__device__ float g_bias[2048];

// bf16 split operands
__device__ __nv_bfloat16 g_xb [N_INTERNAL * KP];
__device__ __nv_bfloat16 g_Wb [2048 * KP];
__device__ __nv_bfloat16 g_Uib[1536 * KP];
__device__ __nv_bfloat16 g_Ufb[ 512 * KP];
__device__ __nv_bfloat16 g_hsb[1024 * KP];
__device__ __nv_bfloat16 g_hlb[4096 * KP];

__device__ __forceinline__ float fast_tanh(float x) {
    float r;
    asm("tanh.approx.f32 %0, %1;" : "=f"(r) : "f"(x));
    return r;
}
__device__ __forceinline__ float fast_sigm(float x) {
    return 0.5f + 0.5f * fast_tanh(0.5f * x);
}
__device__ __forceinline__ void split_bf16(float v, __nv_bfloat16& hi, __nv_bfloat16& lo) {
    hi = __float2bfloat16_rn(v);
    lo = __float2bfloat16_rn(v - __bfloat162float(hi));
}

// ---------------------------------------------------------------------------
__global__ void zero_leaves_kernel(float4* __restrict__ h4, float4* __restrict__ c4)
{
    const int cnt = (N_NODES - N_INTERNAL) * HID / 4;
    int i = blockIdx.x * blockDim.x + threadIdx.x;
    if (i < cnt) {
        float4 z = make_float4(0.f, 0.f, 0.f, 0.f);
        h4[i] = z;
        c4[i] = z;
    }
}

__global__ void conv_x_kernel(const float* __restrict__ x)
{
    int i = blockIdx.x * blockDim.x + threadIdx.x;
    if (i >= N_INTERNAL * 512) return;
    int m = i >> 9, k = i & 511;
    __nv_bfloat16 hi, lo;
    split_bf16(x[(size_t)m * 512 + k], hi, lo);
    __nv_bfloat16* d = g_xb + (size_t)m * KP;
    d[k] = hi; d[512 + k] = hi; d[1024 + k] = lo;
}

__global__ void conv_w_kernel(const float* __restrict__ W_iou, const float* __restrict__ W_f,
                              const float* __restrict__ b_iou, const float* __restrict__ b_f)
{
    int i = blockIdx.x * blockDim.x + threadIdx.x;
    if (i < 2048) g_bias[i] = (i < 1536) ? b_iou[i] : b_f[i - 1536];
    if (i >= 2048 * 512) return;
    int n = i >> 9, k = i & 511;
    float v = (n < 1536) ? W_iou[(size_t)n * 512 + k] : W_f[(size_t)(n - 1536) * 512 + k];
    __nv_bfloat16 hi, lo;
    split_bf16(v, hi, lo);
    __nv_bfloat16* d = g_Wb + (size_t)n * KP;
    d[k] = hi; d[512 + k] = lo; d[1024 + k] = hi;
}

__global__ void conv_u_kernel(const float* __restrict__ U, __nv_bfloat16* __restrict__ dst, int rows)
{
    int i = blockIdx.x * blockDim.x + threadIdx.x;
    if (i >= rows * 512) return;
    int n = i >> 9, k = i & 511;
    __nv_bfloat16 hi, lo;
    split_bf16(U[(size_t)n * 512 + k], hi, lo);
    __nv_bfloat16* d = dst + (size_t)n * KP;
    d[k] = hi; d[512 + k] = lo; d[1024 + k] = hi;
}

__global__ void hsum_conv_kernel(const float* __restrict__ hlev, int M)
{
    int i = blockIdx.x * blockDim.x + threadIdx.x;
    if (i >= M * 512) return;
    int m = i >> 9, k = i & 511;
    const float* p = hlev + (size_t)m * 2048 + k;
    float s = p[0] + p[512] + p[1024] + p[1536];
    __nv_bfloat16 hi, lo;
    split_bf16(s, hi, lo);
    __nv_bfloat16* d = g_hsb + (size_t)m * KP;
    d[k] = hi; d[512 + k] = hi; d[1024 + k] = lo;
}

// ---------------------------------------------------------------------------
// bf16 tensor-core GEMM (NT): C[M,N] = A'[M,KP] * B'[N,KP]^T (+ col bias)
// CTA 128x128, BK=32, 8 warps (2x4), warp tile 64x32 = 4x4 m16n8k16.
// cp.async 2-stage pipeline; ldmatrix fragment loads; smem rows padded to
// 20 u32 (80B) -> conflict-free LDSM & STS.
// Requires N % 128 == 0; M guarded via cp.async src-size zero-fill.
// ---------------------------------------------------------------------------
#define RSTR 20    // u32 per smem row (16 data + 4 pad)

__device__ __forceinline__ void cp16(uint32_t dst, const void* src, int pbytes) {
    asm volatile("cp.async.cg.shared.global [%0], [%1], 16, %2;"
                 :: "r"(dst), "l"(src), "r"(pbytes));
}

__global__ __launch_bounds__(256)
void gemm_bf16_3x(const __nv_bfloat16* __restrict__ A,
                  const __nv_bfloat16* __restrict__ B,
                  float* __restrict__ C, int ldc,
                  const float* __restrict__ bias,
                  int M, int N)
{
    __shared__ __align__(16) uint32_t SA[2][128][RSTR];
    __shared__ __align__(16) uint32_t SB[2][128][RSTR];

    const int t    = threadIdx.x;
    const int lane = t & 31;
    const int warp = t >> 5;
    const int g    = lane >> 2;
    const int tg   = lane & 3;
    const int wm   = warp >> 2;          // 0..1  (M dir, 64 rows)
    const int wn   = warp & 3;           // 0..3  (N dir, 32 cols)
    const int bm   = blockIdx.y * 128;
    const int bn   = blockIdx.x * 128;

    const uint32_t sa0 = (uint32_t)__cvta_generic_to_shared(&SA[0][0][0]);
    const uint32_t sb0 = (uint32_t)__cvta_generic_to_shared(&SB[0][0][0]);
    const uint32_t stgB = 128 * RSTR * 4;           // bytes per stage

    const int lrow = t >> 2;
    const int lseg = t & 3;

    float acc[4][4][4];
#pragma unroll
    for (int mt = 0; mt < 4; mt++)
#pragma unroll
        for (int nt = 0; nt < 4; nt++)
#pragma unroll
            for (int r = 0; r < 4; r++) acc[mt][nt][r] = 0.f;

    auto prefetch = [&](int it, int buf) {
        int k0 = it * 32;                           // bf16 elements
#pragma unroll
        for (int i = 0; i < 2; i++) {
            int row = lrow + i * 64;
            uint32_t da = sa0 + buf * stgB + (row * RSTR + lseg * 4) * 4;
            uint32_t db = sb0 + buf * stgB + (row * RSTR + lseg * 4) * 4;
            int gm = bm + row;
            cp16(da, A + (size_t)gm * KP + k0 + lseg * 8, gm < M ? 16 : 0);
            cp16(db, B + (size_t)(bn + row) * KP + k0 + lseg * 8, 16);
        }
        asm volatile("cp.async.commit_group;");
    };

    prefetch(0, 0);

    const int nit = KP / 32;                        // 48
    for (int it = 0; it < nit; it++) {
        int cur = it & 1;
        if (it + 1 < nit) {
            prefetch(it + 1, cur ^ 1);
            asm volatile("cp.async.wait_group 1;");
        } else {
            asm volatile("cp.async.wait_group 0;");
        }
        __syncthreads();

        uint32_t abase = sa0 + cur * stgB;
        uint32_t bbase = sb0 + cur * stgB;

#pragma unroll
        for (int ks = 0; ks < 2; ks++) {
            // B fragments: 4 n-tiles via ldmatrix.x2 (NO trans: NT layout
            // already yields k-consecutive B fragments)
            uint32_t bf[4][2];
#pragma unroll
            for (int nt = 0; nt < 4; nt++) {
                int nrow = wn * 32 + nt * 8 + (lane & 7);
                int kpo  = ks * 8 + ((lane >> 3) & 1) * 4;
                uint32_t addr = bbase + (nrow * RSTR + kpo) * 4;
                asm volatile("ldmatrix.sync.aligned.m8n8.x2.shared.b16 {%0,%1}, [%2];"
                             : "=r"(bf[nt][0]), "=r"(bf[nt][1]) : "r"(addr));
            }
#pragma unroll
            for (int mt = 0; mt < 4; mt++) {
                int mrow = wm * 64 + mt * 16 + (lane & 7) + ((lane >> 3) & 1) * 8;
                int kpo  = ks * 8 + (lane >> 4) * 4;
                uint32_t addr = abase + (mrow * RSTR + kpo) * 4;
                uint32_t a0, a1, a2, a3;
                asm volatile("ldmatrix.sync.aligned.m8n8.x4.shared.b16 {%0,%1,%2,%3}, [%4];"
                             : "=r"(a0), "=r"(a1), "=r"(a2), "=r"(a3) : "r"(addr));
#pragma unroll
                for (int nt = 0; nt < 4; nt++) {
                    asm volatile(
                        "mma.sync.aligned.m16n8k16.row.col.f32.bf16.bf16.f32 "
                        "{%0,%1,%2,%3}, {%4,%5,%6,%7}, {%8,%9}, {%0,%1,%2,%3};"
                        : "+f"(acc[mt][nt][0]), "+f"(acc[mt][nt][1]),
                          "+f"(acc[mt][nt][2]), "+f"(acc[mt][nt][3])
                        : "r"(a0), "r"(a1), "r"(a2), "r"(a3),
                          "r"(bf[nt][0]), "r"(bf[nt][1]));
                }
            }
        }
        __syncthreads();
    }

    // epilogue: d0:(g,2tg) d1:(g,2tg+1) d2:(g+8,2tg) d3:(g+8,2tg+1)
#pragma unroll
    for (int mt = 0; mt < 4; mt++) {
#pragma unroll
        for (int nt = 0; nt < 4; nt++) {
            int col = bn + wn * 32 + nt * 8 + tg * 2;
            float bx = 0.f, by = 0.f;
            if (bias) { bx = bias[col]; by = bias[col + 1]; }
            int r0 = bm + wm * 64 + mt * 16 + g;
            if (r0 < M) {
                float2 v = make_float2(acc[mt][nt][0] + bx, acc[mt][nt][1] + by);
                *reinterpret_cast<float2*>(C + (size_t)r0 * ldc + col) = v;
            }
            int r1 = r0 + 8;
            if (r1 < M) {
                float2 v = make_float2(acc[mt][nt][2] + bx, acc[mt][nt][3] + by);
                *reinterpret_cast<float2*>(C + (size_t)r1 * ldc + col) = v;
            }
        }
    }
}

// ---------------------------------------------------------------------------
__global__ __launch_bounds__(512)
void act6_kernel(float* __restrict__ h_arr, float* __restrict__ c_arr, int s)
{
    int n = blockIdx.x;
    int d = threadIdx.x;
    const float* wxp = g_wx + (size_t)(s + n) * 2048;
    float i = fast_sigm(wxp[d]);
    float o = fast_sigm(wxp[512 + d]);
    float u = fast_tanh(wxp[1024 + d]);
    float c = i * u;
    float h = o * fast_tanh(c);
    c_arr[(size_t)(s + n) * HID + d] = c;
    h_arr[(size_t)(s + n) * HID + d] = h;
    __nv_bfloat16 hi, lo;
    split_bf16(h, hi, lo);
    __nv_bfloat16* hb = g_hlb + (size_t)n * KP;
    hb[d] = hi; hb[512 + d] = hi; hb[1024 + d] = lo;
}

__global__ __launch_bounds__(512)
void combine_kernel(float* __restrict__ h_arr, float* __restrict__ c_arr, int s)
{
    int n = blockIdx.x;
    int d = threadIdx.x;
    const float* wxp  = g_wx  + (size_t)(s + n) * 2048;
    const float* ioup = g_iou + (size_t)n * 1536;

    float i = fast_sigm(ioup[d]        + wxp[d]);
    float o = fast_sigm(ioup[512 + d]  + wxp[512 + d]);
    float u = fast_tanh(ioup[1024 + d] + wxp[1024 + d]);
    float wxf = wxp[1536 + d];

    float acc = i * u;
    int cbase = 4 * (s + n) + 1;
#pragma unroll
    for (int j = 0; j < 4; j++) {
        float fj = g_f[((size_t)n * 4 + j) * 512 + d] + wxf;
        acc += fj * c_arr[(size_t)(cbase + j) * HID + d];
    }
    float h = o * fast_tanh(acc);
    c_arr[(size_t)(s + n) * HID + d] = acc;
    h_arr[(size_t)(s + n) * HID + d] = h;
    __nv_bfloat16 hi, lo;
    split_bf16(h, hi, lo);
    __nv_bfloat16* hb = g_hlb + (size_t)n * KP;
    hb[d] = hi; hb[512 + d] = hi; hb[1024 + d] = lo;
}

// ---------------------------------------------------------------------------
extern "C" void kernel_launch(void* const* d_in, const int* in_sizes, int n_in,
                              void* d_out, int out_size)
{
    const float* x      = (const float*)d_in[0];
    const float* W_iou  = (const float*)d_in[2];
    const float* b_iou  = (const float*)d_in[3];
    const float* W_f    = (const float*)d_in[4];
    const float* b_f    = (const float*)d_in[5];
    const float* U_iou  = (const float*)d_in[6];
    const float* U_f    = (const float*)d_in[7];

    float* h_arr = (float*)d_out;
    float* c_arr = (float*)d_out + (size_t)N_NODES * HID;

    float *wx, *iou, *fbuf;
    __nv_bfloat16 *xb, *Wb, *Uib, *Ufb, *hsb, *hlb;
    cudaGetSymbolAddress((void**)&wx,  g_wx);
    cudaGetSymbolAddress((void**)&iou, g_iou);
    cudaGetSymbolAddress((void**)&fbuf,g_f);
    cudaGetSymbolAddress((void**)&xb,  g_xb);
    cudaGetSymbolAddress((void**)&Wb,  g_Wb);
    cudaGetSymbolAddress((void**)&Uib, g_Uib);
    cudaGetSymbolAddress((void**)&Ufb, g_Ufb);
    cudaGetSymbolAddress((void**)&hsb, g_hsb);
    cudaGetSymbolAddress((void**)&hlb, g_hlb);
    float* bias;
    cudaGetSymbolAddress((void**)&bias, g_bias);

    // 1. zero leaf rows of h and c
    {
        float4* h4 = (float4*)(h_arr + (size_t)N_INTERNAL * HID);
        float4* c4 = (float4*)(c_arr + (size_t)N_INTERNAL * HID);
        int cnt = (N_NODES - N_INTERNAL) * HID / 4;
        zero_leaves_kernel<<<(cnt + 255) / 256, 256>>>(h4, c4);
    }

    // 2. split-bf16 conversions
    conv_x_kernel<<<(N_INTERNAL * 512 + 255) / 256, 256>>>(x);
    conv_w_kernel<<<(2048 * 512 + 255) / 256, 256>>>(W_iou, W_f, b_iou, b_f);
    conv_u_kernel<<<(1536 * 512 + 255) / 256, 256>>>(U_iou, Uib, 1536);
    conv_u_kernel<<<( 512 * 512 + 255) / 256, 256>>>(U_f,   Ufb,  512);

    // 3. big GEMM: wx[5461 x 2048] = x' @ Wb^T + bias
    {
        dim3 g(2048 / 128, (N_INTERNAL + 127) / 128);
        gemm_bf16_3x<<<g, 256>>>(xb, Wb, wx, 2048, bias, N_INTERNAL, 2048);
    }

    // 4. level 6: nodes [1365, 5461), pure activation (+ split h emit)
    act6_kernel<<<4096, 512>>>(h_arr, c_arr, 1365);

    // 5. levels 5..0
    for (int l = 5; l >= 0; --l) {
        int M  = 1 << (2 * l);
        int s  = (M - 1) / 3;
        int sp = 4 * s + 1;
        const float* hlev = h_arr + (size_t)sp * HID;

        hsum_conv_kernel<<<(M * 512 + 255) / 256, 256>>>(hlev, M);

        {
            dim3 g(1536 / 128, (M + 127) / 128);
            gemm_bf16_3x<<<g, 256>>>(hsb, Uib, iou, 1536, nullptr, M, 1536);
        }
        {
            int Mf = 4 * M;
            dim3 g(512 / 128, (Mf + 127) / 128);
            gemm_bf16_3x<<<g, 256>>>(hlb, Ufb, fbuf, 512, nullptr, Mf, 512);
        }
        combine_kernel<<<M, 512>>>(h_arr, c_arr, s);
    }
}

// round 15
// speedup vs baseline: 3.2256x; 1.0345x over previous
#include <cuda_runtime.h>
#include <cuda_bf16.h>
#include <cstdint>

// ---------------------------------------------------------------------------
// Child-Sum Tree-LSTM, complete 4-ary tree depth 7.
// N_NODES=21845, N_INTERNAL=5461, HID=IN=512.
// Children of level-l rows [s,e) are exactly rows [4s+1, 4e+1) (level l+1).
//
// GEMMs: tensor cores (mma.sync.m16n8k16.bf16) with SPLIT-BF16 3-term fp32
// emulation packed along K:  A'=[Ahi|Ahi|Alo], B'=[Bhi|Blo|Bhi], K'=1536,
// C = Ahi.Bhi + Ahi.Blo + Alo.Bhi  (error ~2^-17, fp32 accumulate).
// R15: 3-stage cp.async ring -> ONE __syncthreads per K-iter (was 2).
// ---------------------------------------------------------------------------

#define N_NODES    21845
#define N_INTERNAL 5461
#define HID        512
#define KP         1536          // packed K' = 3*512

// fp32 scratch
__device__ float g_wx[N_INTERNAL * 2048];      // ~44.7 MB
__device__ float g_iou[1024 * 1536];           // 6 MB
__device__ float g_f[4096 * 512];              // 8 MB
__device__ float g_bias[2048];

// bf16 split operands
__device__ __nv_bfloat16 g_xb [N_INTERNAL * KP];
__device__ __nv_bfloat16 g_Wb [2048 * KP];
__device__ __nv_bfloat16 g_Uib[1536 * KP];
__device__ __nv_bfloat16 g_Ufb[ 512 * KP];
__device__ __nv_bfloat16 g_hsb[1024 * KP];
__device__ __nv_bfloat16 g_hlb[4096 * KP];

__device__ __forceinline__ float fast_tanh(float x) {
    float r;
    asm("tanh.approx.f32 %0, %1;" : "=f"(r) : "f"(x));
    return r;
}
__device__ __forceinline__ float fast_sigm(float x) {
    return 0.5f + 0.5f * fast_tanh(0.5f * x);
}
__device__ __forceinline__ void split_bf16(float v, __nv_bfloat16& hi, __nv_bfloat16& lo) {
    hi = __float2bfloat16_rn(v);
    lo = __float2bfloat16_rn(v - __bfloat162float(hi));
}

// ---------------------------------------------------------------------------
__global__ void zero_leaves_kernel(float4* __restrict__ h4, float4* __restrict__ c4)
{
    const int cnt = (N_NODES - N_INTERNAL) * HID / 4;
    int i = blockIdx.x * blockDim.x + threadIdx.x;
    if (i < cnt) {
        float4 z = make_float4(0.f, 0.f, 0.f, 0.f);
        h4[i] = z;
        c4[i] = z;
    }
}

__global__ void conv_x_kernel(const float* __restrict__ x)
{
    int i = blockIdx.x * blockDim.x + threadIdx.x;
    if (i >= N_INTERNAL * 512) return;
    int m = i >> 9, k = i & 511;
    __nv_bfloat16 hi, lo;
    split_bf16(x[(size_t)m * 512 + k], hi, lo);
    __nv_bfloat16* d = g_xb + (size_t)m * KP;
    d[k] = hi; d[512 + k] = hi; d[1024 + k] = lo;
}

__global__ void conv_w_kernel(const float* __restrict__ W_iou, const float* __restrict__ W_f,
                              const float* __restrict__ b_iou, const float* __restrict__ b_f)
{
    int i = blockIdx.x * blockDim.x + threadIdx.x;
    if (i < 2048) g_bias[i] = (i < 1536) ? b_iou[i] : b_f[i - 1536];
    if (i >= 2048 * 512) return;
    int n = i >> 9, k = i & 511;
    float v = (n < 1536) ? W_iou[(size_t)n * 512 + k] : W_f[(size_t)(n - 1536) * 512 + k];
    __nv_bfloat16 hi, lo;
    split_bf16(v, hi, lo);
    __nv_bfloat16* d = g_Wb + (size_t)n * KP;
    d[k] = hi; d[512 + k] = lo; d[1024 + k] = hi;
}

__global__ void conv_u_kernel(const float* __restrict__ U, __nv_bfloat16* __restrict__ dst, int rows)
{
    int i = blockIdx.x * blockDim.x + threadIdx.x;
    if (i >= rows * 512) return;
    int n = i >> 9, k = i & 511;
    __nv_bfloat16 hi, lo;
    split_bf16(U[(size_t)n * 512 + k], hi, lo);
    __nv_bfloat16* d = dst + (size_t)n * KP;
    d[k] = hi; d[512 + k] = lo; d[1024 + k] = hi;
}

__global__ void hsum_conv_kernel(const float* __restrict__ hlev, int M)
{
    int i = blockIdx.x * blockDim.x + threadIdx.x;
    if (i >= M * 512) return;
    int m = i >> 9, k = i & 511;
    const float* p = hlev + (size_t)m * 2048 + k;
    float s = p[0] + p[512] + p[1024] + p[1536];
    __nv_bfloat16 hi, lo;
    split_bf16(s, hi, lo);
    __nv_bfloat16* d = g_hsb + (size_t)m * KP;
    d[k] = hi; d[512 + k] = hi; d[1024 + k] = lo;
}

// ---------------------------------------------------------------------------
// bf16 tensor-core GEMM (NT): C[M,N] = A'[M,KP] * B'[N,KP]^T (+ col bias)
// CTA 128x128, BK=32, 8 warps (2x4), warp tile 64x32 = 4x4 m16n8k16.
// 3-stage cp.async ring (one __syncthreads per iter); ldmatrix fragments;
// smem rows padded to 20 u32 (80B) -> conflict-free LDSM & STS.
// Requires N % 128 == 0; M guarded via cp.async src-size zero-fill.
// ---------------------------------------------------------------------------
#define RSTR 20    // u32 per smem row (16 data + 4 pad)

__device__ __forceinline__ void cp16(uint32_t dst, const void* src, int pbytes) {
    asm volatile("cp.async.cg.shared.global [%0], [%1], 16, %2;"
                 :: "r"(dst), "l"(src), "r"(pbytes));
}

__global__ __launch_bounds__(256)
void gemm_bf16_3x(const __nv_bfloat16* __restrict__ A,
                  const __nv_bfloat16* __restrict__ B,
                  float* __restrict__ C, int ldc,
                  const float* __restrict__ bias,
                  int M, int N)
{
    __shared__ __align__(16) uint32_t SA[3][128][RSTR];
    __shared__ __align__(16) uint32_t SB[3][128][RSTR];

    const int t    = threadIdx.x;
    const int lane = t & 31;
    const int warp = t >> 5;
    const int g    = lane >> 2;
    const int tg   = lane & 3;
    const int wm   = warp >> 2;          // 0..1  (M dir, 64 rows)
    const int wn   = warp & 3;           // 0..3  (N dir, 32 cols)
    const int bm   = blockIdx.y * 128;
    const int bn   = blockIdx.x * 128;

    const uint32_t sa0 = (uint32_t)__cvta_generic_to_shared(&SA[0][0][0]);
    const uint32_t sb0 = (uint32_t)__cvta_generic_to_shared(&SB[0][0][0]);
    const uint32_t stgB = 128 * RSTR * 4;           // bytes per stage

    const int lrow = t >> 2;
    const int lseg = t & 3;

    float acc[4][4][4];
#pragma unroll
    for (int mt = 0; mt < 4; mt++)
#pragma unroll
        for (int nt = 0; nt < 4; nt++)
#pragma unroll
            for (int r = 0; r < 4; r++) acc[mt][nt][r] = 0.f;

    auto prefetch = [&](int it, int buf) {
        int k0 = it * 32;                           // bf16 elements
#pragma unroll
        for (int i = 0; i < 2; i++) {
            int row = lrow + i * 64;
            uint32_t da = sa0 + buf * stgB + (row * RSTR + lseg * 4) * 4;
            uint32_t db = sb0 + buf * stgB + (row * RSTR + lseg * 4) * 4;
            int gm = bm + row;
            cp16(da, A + (size_t)gm * KP + k0 + lseg * 8, gm < M ? 16 : 0);
            cp16(db, B + (size_t)(bn + row) * KP + k0 + lseg * 8, 16);
        }
        asm volatile("cp.async.commit_group;");
    };

    const int nit = KP / 32;                        // 48
    prefetch(0, 0);
    prefetch(1, 1);

    for (int it = 0; it < nit; it++) {
        // stage `it` must be complete: with groups in-order, <=1 outstanding
        // suffices except on the last iteration (then 0).
        if (it == nit - 1)
            asm volatile("cp.async.wait_group 0;");
        else
            asm volatile("cp.async.wait_group 1;");
        __syncthreads();

        // prefetch stage it+2 into ring slot (it+2)%3 — safe after the sync:
        // every warp finished reading that slot during iteration it-1.
        if (it + 2 < nit) prefetch(it + 2, (it + 2) % 3);

        const int cur = it % 3;
        uint32_t abase = sa0 + cur * stgB;
        uint32_t bbase = sb0 + cur * stgB;

#pragma unroll
        for (int ks = 0; ks < 2; ks++) {
            // B fragments: 4 n-tiles via ldmatrix.x2 (no .trans: NT layout
            // already yields k-consecutive B fragments)
            uint32_t bf[4][2];
#pragma unroll
            for (int nt = 0; nt < 4; nt++) {
                int nrow = wn * 32 + nt * 8 + (lane & 7);
                int kpo  = ks * 8 + ((lane >> 3) & 1) * 4;
                uint32_t addr = bbase + (nrow * RSTR + kpo) * 4;
                asm volatile("ldmatrix.sync.aligned.m8n8.x2.shared.b16 {%0,%1}, [%2];"
                             : "=r"(bf[nt][0]), "=r"(bf[nt][1]) : "r"(addr));
            }
#pragma unroll
            for (int mt = 0; mt < 4; mt++) {
                int mrow = wm * 64 + mt * 16 + (lane & 7) + ((lane >> 3) & 1) * 8;
                int kpo  = ks * 8 + (lane >> 4) * 4;
                uint32_t addr = abase + (mrow * RSTR + kpo) * 4;
                uint32_t a0, a1, a2, a3;
                asm volatile("ldmatrix.sync.aligned.m8n8.x4.shared.b16 {%0,%1,%2,%3}, [%4];"
                             : "=r"(a0), "=r"(a1), "=r"(a2), "=r"(a3) : "r"(addr));
#pragma unroll
                for (int nt = 0; nt < 4; nt++) {
                    asm volatile(
                        "mma.sync.aligned.m16n8k16.row.col.f32.bf16.bf16.f32 "
                        "{%0,%1,%2,%3}, {%4,%5,%6,%7}, {%8,%9}, {%0,%1,%2,%3};"
                        : "+f"(acc[mt][nt][0]), "+f"(acc[mt][nt][1]),
                          "+f"(acc[mt][nt][2]), "+f"(acc[mt][nt][3])
                        : "r"(a0), "r"(a1), "r"(a2), "r"(a3),
                          "r"(bf[nt][0]), "r"(bf[nt][1]));
                }
            }
        }
    }

    // epilogue: d0:(g,2tg) d1:(g,2tg+1) d2:(g+8,2tg) d3:(g+8,2tg+1)
#pragma unroll
    for (int mt = 0; mt < 4; mt++) {
#pragma unroll
        for (int nt = 0; nt < 4; nt++) {
            int col = bn + wn * 32 + nt * 8 + tg * 2;
            float bx = 0.f, by = 0.f;
            if (bias) { bx = bias[col]; by = bias[col + 1]; }
            int r0 = bm + wm * 64 + mt * 16 + g;
            if (r0 < M) {
                float2 v = make_float2(acc[mt][nt][0] + bx, acc[mt][nt][1] + by);
                *reinterpret_cast<float2*>(C + (size_t)r0 * ldc + col) = v;
            }
            int r1 = r0 + 8;
            if (r1 < M) {
                float2 v = make_float2(acc[mt][nt][2] + bx, acc[mt][nt][3] + by);
                *reinterpret_cast<float2*>(C + (size_t)r1 * ldc + col) = v;
            }
        }
    }
}

// ---------------------------------------------------------------------------
__global__ __launch_bounds__(512)
void act6_kernel(float* __restrict__ h_arr, float* __restrict__ c_arr, int s)
{
    int n = blockIdx.x;
    int d = threadIdx.x;
    const float* wxp = g_wx + (size_t)(s + n) * 2048;
    float i = fast_sigm(wxp[d]);
    float o = fast_sigm(wxp[512 + d]);
    float u = fast_tanh(wxp[1024 + d]);
    float c = i * u;
    float h = o * fast_tanh(c);
    c_arr[(size_t)(s + n) * HID + d] = c;
    h_arr[(size_t)(s + n) * HID + d] = h;
    __nv_bfloat16 hi, lo;
    split_bf16(h, hi, lo);
    __nv_bfloat16* hb = g_hlb + (size_t)n * KP;
    hb[d] = hi; hb[512 + d] = hi; hb[1024 + d] = lo;
}

__global__ __launch_bounds__(512)
void combine_kernel(float* __restrict__ h_arr, float* __restrict__ c_arr, int s)
{
    int n = blockIdx.x;
    int d = threadIdx.x;
    const float* wxp  = g_wx  + (size_t)(s + n) * 2048;
    const float* ioup = g_iou + (size_t)n * 1536;

    float i = fast_sigm(ioup[d]        + wxp[d]);
    float o = fast_sigm(ioup[512 + d]  + wxp[512 + d]);
    float u = fast_tanh(ioup[1024 + d] + wxp[1024 + d]);
    float wxf = wxp[1536 + d];

    float acc = i * u;
    int cbase = 4 * (s + n) + 1;
#pragma unroll
    for (int j = 0; j < 4; j++) {
        float fj = g_f[((size_t)n * 4 + j) * 512 + d] + wxf;
        acc += fj * c_arr[(size_t)(cbase + j) * HID + d];
    }
    float h = o * fast_tanh(acc);
    c_arr[(size_t)(s + n) * HID + d] = acc;
    h_arr[(size_t)(s + n) * HID + d] = h;
    __nv_bfloat16 hi, lo;
    split_bf16(h, hi, lo);
    __nv_bfloat16* hb = g_hlb + (size_t)n * KP;
    hb[d] = hi; hb[512 + d] = hi; hb[1024 + d] = lo;
}

// ---------------------------------------------------------------------------
extern "C" void kernel_launch(void* const* d_in, const int* in_sizes, int n_in,
                              void* d_out, int out_size)
{
    const float* x      = (const float*)d_in[0];
    const float* W_iou  = (const float*)d_in[2];
    const float* b_iou  = (const float*)d_in[3];
    const float* W_f    = (const float*)d_in[4];
    const float* b_f    = (const float*)d_in[5];
    const float* U_iou  = (const float*)d_in[6];
    const float* U_f    = (const float*)d_in[7];

    float* h_arr = (float*)d_out;
    float* c_arr = (float*)d_out + (size_t)N_NODES * HID;

    float *wx, *iou, *fbuf;
    __nv_bfloat16 *xb, *Wb, *Uib, *Ufb, *hsb, *hlb;
    cudaGetSymbolAddress((void**)&wx,  g_wx);
    cudaGetSymbolAddress((void**)&iou, g_iou);
    cudaGetSymbolAddress((void**)&fbuf,g_f);
    cudaGetSymbolAddress((void**)&xb,  g_xb);
    cudaGetSymbolAddress((void**)&Wb,  g_Wb);
    cudaGetSymbolAddress((void**)&Uib, g_Uib);
    cudaGetSymbolAddress((void**)&Ufb, g_Ufb);
    cudaGetSymbolAddress((void**)&hsb, g_hsb);
    cudaGetSymbolAddress((void**)&hlb, g_hlb);
    float* bias;
    cudaGetSymbolAddress((void**)&bias, g_bias);

    // 1. zero leaf rows of h and c
    {
        float4* h4 = (float4*)(h_arr + (size_t)N_INTERNAL * HID);
        float4* c4 = (float4*)(c_arr + (size_t)N_INTERNAL * HID);
        int cnt = (N_NODES - N_INTERNAL) * HID / 4;
        zero_leaves_kernel<<<(cnt + 255) / 256, 256>>>(h4, c4);
    }

    // 2. split-bf16 conversions
    conv_x_kernel<<<(N_INTERNAL * 512 + 255) / 256, 256>>>(x);
    conv_w_kernel<<<(2048 * 512 + 255) / 256, 256>>>(W_iou, W_f, b_iou, b_f);
    conv_u_kernel<<<(1536 * 512 + 255) / 256, 256>>>(U_iou, Uib, 1536);
    conv_u_kernel<<<( 512 * 512 + 255) / 256, 256>>>(U_f,   Ufb,  512);

    // 3. big GEMM: wx[5461 x 2048] = x' @ Wb^T + bias
    {
        dim3 g(2048 / 128, (N_INTERNAL + 127) / 128);
        gemm_bf16_3x<<<g, 256>>>(xb, Wb, wx, 2048, bias, N_INTERNAL, 2048);
    }

    // 4. level 6: nodes [1365, 5461), pure activation (+ split h emit)
    act6_kernel<<<4096, 512>>>(h_arr, c_arr, 1365);

    // 5. levels 5..0
    for (int l = 5; l >= 0; --l) {
        int M  = 1 << (2 * l);
        int s  = (M - 1) / 3;
        int sp = 4 * s + 1;
        const float* hlev = h_arr + (size_t)sp * HID;

        hsum_conv_kernel<<<(M * 512 + 255) / 256, 256>>>(hlev, M);

        {
            dim3 g(1536 / 128, (M + 127) / 128);
            gemm_bf16_3x<<<g, 256>>>(hsb, Uib, iou, 1536, nullptr, M, 1536);
        }
        {
            int Mf = 4 * M;
            dim3 g(512 / 128, (Mf + 127) / 128);
            gemm_bf16_3x<<<g, 256>>>(hlb, Ufb, fbuf, 512, nullptr, Mf, 512);
        }
        combine_kernel<<<M, 512>>>(h_arr, c_arr, s);
    }
}